// round 1
// baseline (speedup 1.0000x reference)
#include <cuda_runtime.h>

// ---------------------------------------------------------------------------
// Problem constants (derived from reference):
//   B=8, H=W=256, I_DIM=64, K_DIM=64 (per stream), V_DIM=32 (per stream)
//   NH=2 heads -> hd_k=32, hd_v=16
//   unfold params for (width=256, P=7, NK=4): p=7, stride=21, dilation=4, nk=12
//   => 12x12 = 144 patches of 7x7=49 pixels, positions 21*i + 4*j all DISTINCT
//   => fold has no overlap; non-sampled pixels of output are exactly bp[c].
// ---------------------------------------------------------------------------

#define BDIM 384

// smem layout (float offsets), dynamic smem
constexpr int oWk  = 0;                 // 128 rows x 64 (stride 68)
constexpr int oWv  = oWk + 128 * 68;    // 8704  : 64 rows x 64 (stride 68)
constexpr int oWp  = oWv + 64 * 68;     // 13056 : 64 rows x 64 (stride 68)
constexpr int obk  = oWp + 64 * 68;     // 17408 : 128
constexpr int obv  = obk + 128;         // 17536 : 64
constexpr int obp  = obv + 64;          // 17600 : 64
constexpr int oX   = obp + 64;          // 17664 : 2*49 rows x 64 (stride 68)
constexpr int oE   = oX;                // alias (X dead after conv): 98 rows x 49 (stride 52)
constexpr int oK   = oX + 2 * 49 * 68;  // 24328 : 2*49 rows x 64 (stride 68)
constexpr int oO   = oK;                // alias (K dead after kk): 49 rows x 64 (stride 68)
constexpr int oOut = oK + 49 * 68;      // 27660 : 49 rows x 64 (stride 68)
constexpr int oV   = oK + 2 * 49 * 68;  // 30992 : 2*49 rows x 32 (stride 36)
constexpr int oCS  = oV + 2 * 49 * 36;  // 34520 : 98 (1/colsum)
constexpr int oRS  = oCS + 98;          // 34618 : 98 (1/rowsum)
constexpr int SMEMF = oRS + 98;         // 34716 floats
constexpr int SMEM_BYTES = SMEMF * 4;   // 138864 bytes

__global__ void fill_bias_kernel(float* __restrict__ out, const float* __restrict__ bp) {
    // out[b][c][h][w] = bp[c]; one float4 per thread. Total float4 = 8*64*65536/4.
    unsigned i = blockIdx.x * blockDim.x + threadIdx.x;    // < 8388608
    int c = (i >> 14) & 63;                                // 16384 float4 per plane
    float v = __ldg(&bp[c]);
    reinterpret_cast<float4*>(out)[i] = make_float4(v, v, v, v);
}

__global__ void __launch_bounds__(BDIM, 1)
attn_patch_kernel(const float* __restrict__ x1, const float* __restrict__ x2,
                  const float* __restrict__ Wk, const float* __restrict__ bk,
                  const float* __restrict__ Wv, const float* __restrict__ bv,
                  const float* __restrict__ Wp, const float* __restrict__ bp,
                  float* __restrict__ out) {
    extern __shared__ __align__(16) float sm[];
    const int tid  = threadIdx.x;
    const int lane = tid & 31;
    const int wid  = tid >> 5;

    const int bidx = blockIdx.x;      // 0..1151
    const int b  = bidx / 144;
    const int s  = bidx % 144;
    const int si = s / 12, sj = s % 12;

    // ---------------- Phase 0: stage weights + biases into smem -------------
    for (int idx = tid; idx < 128 * 64; idx += BDIM) {
        int r = idx >> 6, c = idx & 63;
        sm[oWk + r * 68 + c] = Wk[idx];
    }
    for (int idx = tid; idx < 64 * 64; idx += BDIM) {
        int r = idx >> 6, c = idx & 63;
        sm[oWv + r * 68 + c] = Wv[idx];
        sm[oWp + r * 68 + c] = Wp[idx];
    }
    for (int idx = tid; idx < 128; idx += BDIM) sm[obk + idx] = bk[idx];
    if (tid < 64) { sm[obv + tid] = bv[tid]; sm[obp + tid] = bp[tid]; }

    // ---------------- Phase 1: gather x1/x2 at the 49 patch pixels ----------
    // sX[st][p][c], row stride 68
    for (int idx = tid; idx < 2 * 64 * 49; idx += BDIM) {
        int st = idx / 3136;
        int r  = idx % 3136;
        int c  = r / 49;
        int p  = r % 49;
        int px = p / 7, py = p % 7;
        int h = si * 21 + px * 4, w = sj * 21 + py * 4;
        const float* xp = st ? x2 : x1;
        sm[oX + (st * 49 + p) * 68 + c] = __ldg(&xp[((b * 64 + c) * 256 + h) * 256 + w]);
    }
    __syncthreads();

    // ---------------- Phase 2: 1x1 convs -> k1,k2 (64ch each), v1,v2 (32ch) -
    // Warps 0-7: K (st = wid/4, 16 oc each). Warps 8-11: V (16 oc each).
    {
        int isV = (wid >= 8);
        int st, ocb, wbase, bbase, obase, ostride;
        if (!isV) {
            st = wid >> 2; ocb = (wid & 3) * 16;
            wbase = oWk + (st * 64 + ocb) * 68;
            bbase = obk + st * 64 + ocb;
            obase = oK + (st * 49) * 68 + ocb;
            ostride = 68;
        } else {
            int w2 = wid - 8;
            st = w2 >> 1; ocb = (w2 & 1) * 16;
            wbase = oWv + (st * 32 + ocb) * 68;
            bbase = obv + st * 32 + ocb;
            obase = oV + (st * 49) * 36 + ocb;
            ostride = 36;
        }
        for (int half = 0; half < 2; half++) {
            int p = lane + half * 32;
            if (p < 49) {
                float acc[16];
#pragma unroll
                for (int t = 0; t < 16; t++) acc[t] = sm[bbase + t];
                const float4* xrow = reinterpret_cast<const float4*>(&sm[oX + (st * 49 + p) * 68]);
#pragma unroll
                for (int i4 = 0; i4 < 16; i4++) {
                    float4 xv = xrow[i4];
#pragma unroll
                    for (int t = 0; t < 16; t++) {
                        float4 wv = *reinterpret_cast<const float4*>(&sm[wbase + t * 68 + i4 * 4]);
                        acc[t] += xv.x * wv.x + xv.y * wv.y + xv.z * wv.z + xv.w * wv.w;
                    }
                }
#pragma unroll
                for (int t = 0; t < 16; t++) sm[obase + p * ostride + t] = acc[t];
            }
        }
    }
    __syncthreads();

    // ---------------- Phase 3: kk = scale * k1 . k2 (per head), E = exp(kk) -
    // |kk| << 10 here, so softmax without max-subtraction is numerically safe.
    const float SCALE = 0.17677669529663687f;  // 1/sqrt(32)
    for (int task = tid; task < 2 * 13 * 13; task += BDIM) {
        int n  = task / 169;
        int r  = task % 169;
        int xg = r / 13, yg = r % 13;
        float acc[4][4] = {};
        int kb1 = oK + (xg * 4) * 68 + n * 32;          // k1 rows
        int kb2 = oK + (49 + yg * 4) * 68 + n * 32;     // k2 rows
#pragma unroll
        for (int i4 = 0; i4 < 8; i4++) {
            float4 a[4], c4[4];
#pragma unroll
            for (int xx = 0; xx < 4; xx++)
                a[xx] = *reinterpret_cast<const float4*>(&sm[kb1 + xx * 68 + i4 * 4]);
#pragma unroll
            for (int yy = 0; yy < 4; yy++)
                c4[yy] = *reinterpret_cast<const float4*>(&sm[kb2 + yy * 68 + i4 * 4]);
#pragma unroll
            for (int xx = 0; xx < 4; xx++)
#pragma unroll
                for (int yy = 0; yy < 4; yy++)
                    acc[xx][yy] += a[xx].x * c4[yy].x + a[xx].y * c4[yy].y +
                                   a[xx].z * c4[yy].z + a[xx].w * c4[yy].w;
        }
#pragma unroll
        for (int xx = 0; xx < 4; xx++) {
            int x = xg * 4 + xx;
#pragma unroll
            for (int yy = 0; yy < 4; yy++) {
                int y = yg * 4 + yy;
                if (x < 49 && y < 49)
                    sm[oE + (n * 49 + x) * 52 + y] = __expf(acc[xx][yy] * SCALE);
            }
        }
    }
    __syncthreads();

    // ---------------- Phase 4: reciprocal column / row sums of E ------------
    for (int idx = tid; idx < 196; idx += BDIM) {
        int half = idx / 98;
        int r = idx % 98;
        int n = r / 49, q = r % 49;
        float ssum = 0.f;
        if (half == 0) {  // colsum over x at y=q
            for (int x = 0; x < 49; x++) ssum += sm[oE + (n * 49 + x) * 52 + q];
            sm[oCS + r] = 1.f / ssum;
        } else {          // rowsum over y at x=q
            for (int y = 0; y < 49; y++) ssum += sm[oE + (n * 49 + q) * 52 + y];
            sm[oRS + r] = 1.f / ssum;
        }
    }
    __syncthreads();

    // ---------------- Phase 5: o1 (softmax over x) and o2 (softmax over y) --
    // sO[p][c]: c in [0,32) = o1 channels (n*16+d), c in [32,64) = o2 channels
    for (int task = tid; task < 784; task += BDIM) {
        int which = task / 392;
        int r = task % 392;
        int n = r / 196;
        int r2 = r % 196;
        int p = r2 >> 2;
        int dg = r2 & 3;
        float a0 = 0.f, a1a = 0.f, a2a = 0.f, a3a = 0.f;
        if (which == 0) {
            // o1[d, y=p] = (1/colsum[y]) sum_x E[x][y] * v1[x][d]
            int eb = oE + n * 49 * 52 + p;
            int vb = oV + n * 16 + dg * 4;
#pragma unroll 7
            for (int k = 0; k < 49; k++) {
                float e = sm[eb + k * 52];
                float4 v4 = *reinterpret_cast<const float4*>(&sm[vb + k * 36]);
                a0 += e * v4.x; a1a += e * v4.y; a2a += e * v4.z; a3a += e * v4.w;
            }
            float f = sm[oCS + n * 49 + p];
            int ob = oO + p * 68 + n * 16 + dg * 4;
            sm[ob + 0] = a0 * f; sm[ob + 1] = a1a * f; sm[ob + 2] = a2a * f; sm[ob + 3] = a3a * f;
        } else {
            // o2[d, x=p] = (1/rowsum[x]) sum_y E[x][y] * v2[y][d]
            int eb = oE + (n * 49 + p) * 52;
            int vb = oV + 49 * 36 + n * 16 + dg * 4;
#pragma unroll 7
            for (int k = 0; k < 49; k++) {
                float e = sm[eb + k];
                float4 v4 = *reinterpret_cast<const float4*>(&sm[vb + k * 36]);
                a0 += e * v4.x; a1a += e * v4.y; a2a += e * v4.z; a3a += e * v4.w;
            }
            float f = sm[oRS + n * 49 + p];
            int ob = oO + p * 68 + 32 + n * 16 + dg * 4;
            sm[ob + 0] = a0 * f; sm[ob + 1] = a1a * f; sm[ob + 2] = a2a * f; sm[ob + 3] = a3a * f;
        }
    }
    __syncthreads();

    // ---------------- Phase 6: final 64x64 projection + bias ----------------
    for (int task = tid; task < 784; task += BDIM) {
        int p = task >> 4;
        int cg = task & 15;
        float acc[4];
#pragma unroll
        for (int t = 0; t < 4; t++) acc[t] = sm[obp + cg * 4 + t];
#pragma unroll
        for (int i4 = 0; i4 < 16; i4++) {
            float4 o4 = *reinterpret_cast<const float4*>(&sm[oO + p * 68 + i4 * 4]);
#pragma unroll
            for (int t = 0; t < 4; t++) {
                float4 w4 = *reinterpret_cast<const float4*>(&sm[oWp + (cg * 4 + t) * 68 + i4 * 4]);
                acc[t] += o4.x * w4.x + o4.y * w4.y + o4.z * w4.z + o4.w * w4.w;
            }
        }
#pragma unroll
        for (int t = 0; t < 4; t++) sm[oOut + p * 68 + cg * 4 + t] = acc[t];
    }
    __syncthreads();

    // ---------------- Phase 7: scatter stores (c outer -> rows coalesce) ----
    for (int idx = tid; idx < 64 * 49; idx += BDIM) {
        int c = idx / 49;
        int p = idx % 49;
        int px = p / 7, py = p % 7;
        int h = si * 21 + px * 4, w = sj * 21 + py * 4;
        out[((b * 64 + c) * 256 + h) * 256 + w] = sm[oOut + p * 68 + c];
    }
}

extern "C" void kernel_launch(void* const* d_in, const int* in_sizes, int n_in,
                              void* d_out, int out_size) {
    const float* x1 = (const float*)d_in[0];
    const float* x2 = (const float*)d_in[1];
    const float* Wk = (const float*)d_in[2];
    const float* bk = (const float*)d_in[3];
    const float* Wv = (const float*)d_in[4];
    const float* bv = (const float*)d_in[5];
    const float* Wp = (const float*)d_in[6];
    const float* bp = (const float*)d_in[7];
    float* out = (float*)d_out;

    // 1) fill with bias (non-sampled pixels stay at bp[c])
    fill_bias_kernel<<<32768, 256>>>(out, bp);

    // 2) per-patch fused conv + bilinear attention + projection + scatter
    cudaFuncSetAttribute(attn_patch_kernel,
                         cudaFuncAttributeMaxDynamicSharedMemorySize, SMEM_BYTES);
    attn_patch_kernel<<<1152, BDIM, SMEM_BYTES>>>(x1, x2, Wk, bk, Wv, bv, Wp, bp, out);
}

// round 2
// speedup vs baseline: 1.4017x; 1.4017x over previous
#include <cuda_runtime.h>

// ---------------------------------------------------------------------------
// B=8, H=W=256, I_DIM=64, K_DIM=64/stream, V_DIM=32/stream, NH=2 (hd_k=32, hd_v=16)
// unfold(256, P=7, NK=4) -> p=7, stride=21, dilation=4, nk=12
// => 144 patches of 49 pixels; positions 21*i+4*j are all distinct
// => fold has no overlap; non-sampled output pixels are exactly bp[c].
// ---------------------------------------------------------------------------

#define BDIM 512   // 16 warps

// ---- smem layout (float offsets) ----
// Odd strides (65, 53) give conflict-free lane-indexed scalar access in both
// row and column direction. Stride 68 kept where float4 loads are needed.
constexpr int oWk  = 0;                   // Wk: 128 x 64 (stride 68) ; later aliased by Wp (64 x 68)
constexpr int oWv  = oWk + 128 * 68;      // 8704 : Wv 64 x 64 (stride 68)
constexpr int obk  = oWv + 64 * 68;       // 13056 : 128
constexpr int obv  = obk + 128;           // 13184 : 64
constexpr int obp  = obv + 64;            // 13248 : 64
constexpr int oA   = obp + 64;            // 13312 : region A = max(X 2*49*68=6664, E 98*53=5194)
constexpr int oX   = oA;                  //   X[st*49+p][c] stride 68 (float4)
constexpr int oE   = oA;                  //   E[(n*49+x)*53 + y]
constexpr int oB   = oA + 6664;           // 19976 : region B = max(K 98*65=6370, OT 3392 + Out 3136 = 6528)
constexpr int oK   = oB;                  //   K[(st*49+p)*65 + c]
constexpr int oOT  = oB;                  //   OT[i*53 + p], i in [0,64)
constexpr int oOut = oB + 64 * 53;        //   Out[c*49 + p]
constexpr int oV   = oB + 6528;           // 26504 : V[(st*49+p)*36 + d] (float4 broadcast reads)
constexpr int oCS  = oV + 2 * 49 * 36;    // 30032 : 98  (1/colsum per (n,y))
constexpr int oRS  = oCS + 98;            // 30130 : 98  (1/rowsum per (n,x))
constexpr int SMEMF = oRS + 98;           // 30228 floats
constexpr int SMEM_BYTES = SMEMF * 4;     // 120912 bytes

__global__ void fill_bias_kernel(float* __restrict__ out, const float* __restrict__ bp) {
    unsigned i = blockIdx.x * blockDim.x + threadIdx.x;    // < 8388608 float4
    int c = (i >> 14) & 63;                                // 16384 float4 per plane
    float v = __ldg(&bp[c]);
    reinterpret_cast<float4*>(out)[i] = make_float4(v, v, v, v);
}

__global__ void __launch_bounds__(BDIM, 1)
attn_patch_kernel(const float* __restrict__ x1, const float* __restrict__ x2,
                  const float* __restrict__ Wk, const float* __restrict__ bk,
                  const float* __restrict__ Wv, const float* __restrict__ bv,
                  const float* __restrict__ Wp, const float* __restrict__ bp,
                  float* __restrict__ out) {
    extern __shared__ __align__(16) float sm[];
    const int tid  = threadIdx.x;
    const int lane = tid & 31;
    const int wid  = tid >> 5;

    const int bidx = blockIdx.x;      // 0..1151
    const int b  = bidx / 144;
    const int s  = bidx % 144;
    const int si = s / 12, sj = s % 12;

    // ---------------- Phase 0: stage Wk, Wv, biases ----------------
    for (int idx = tid; idx < 128 * 64; idx += BDIM) {
        int r = idx >> 6, c = idx & 63;
        sm[oWk + r * 68 + c] = Wk[idx];
    }
    for (int idx = tid; idx < 64 * 64; idx += BDIM) {
        int r = idx >> 6, c = idx & 63;
        sm[oWv + r * 68 + c] = Wv[idx];
    }
    for (int idx = tid; idx < 128; idx += BDIM) sm[obk + idx] = bk[idx];
    if (tid < 64) { sm[obv + tid] = bv[tid]; sm[obp + tid] = bp[tid]; }

    // ---------------- Phase 1: gather x1/x2 at the 49 patch pixels ----------
    for (int idx = tid; idx < 2 * 64 * 49; idx += BDIM) {
        int st = idx / 3136;
        int r  = idx % 3136;
        int c  = r / 49;
        int p  = r % 49;
        int px = p / 7, py = p % 7;
        int h = si * 21 + px * 4, w = sj * 21 + py * 4;
        const float* xp = st ? x2 : x1;
        sm[oX + (st * 49 + p) * 68 + c] = __ldg(&xp[((b * 64 + c) * 256 + h) * 256 + w]);
    }
    __syncthreads();

    // ---------------- Phase 2: 1x1 convs -> K (2x49x64, stride 65), V (2x49x32, stride 36)
    // 24 warp-tasks: (job 0..11, half 0..1). job 0-7: K 16-oc groups; job 8-11: V 16-oc groups.
    for (int t = wid; t < 24; t += 16) {
        int job  = t >> 1;
        int half = t & 1;
        int p = lane + half * 32;
        if (p >= 49) continue;
        int isV = (job >= 8);
        int st, ocb, wbase, bbase;
        if (!isV) {
            st = job >> 2; ocb = (job & 3) * 16;
            wbase = oWk + (st * 64 + ocb) * 68;
            bbase = obk + st * 64 + ocb;
        } else {
            int w2 = job - 8;
            st = w2 >> 1; ocb = (w2 & 1) * 16;
            wbase = oWv + (st * 32 + ocb) * 68;
            bbase = obv + st * 32 + ocb;
        }
        float acc[16];
#pragma unroll
        for (int q = 0; q < 16; q++) acc[q] = sm[bbase + q];
        const float4* xrow = reinterpret_cast<const float4*>(&sm[oX + (st * 49 + p) * 68]);
#pragma unroll
        for (int i4 = 0; i4 < 16; i4++) {
            float4 xv = xrow[i4];
#pragma unroll
            for (int q = 0; q < 16; q++) {
                float4 wv = *reinterpret_cast<const float4*>(&sm[wbase + q * 68 + i4 * 4]);
                acc[q] += xv.x * wv.x + xv.y * wv.y + xv.z * wv.z + xv.w * wv.w;
            }
        }
        if (!isV) {
            int ob = oK + (st * 49 + p) * 65 + ocb;
#pragma unroll
            for (int q = 0; q < 16; q++) sm[ob + q] = acc[q];     // lane stride 65 ≡ 1 mod 32: conflict-free
        } else {
            int ob = oV + (st * 49 + p) * 36 + ocb;
#pragma unroll
            for (int q4 = 0; q4 < 4; q4++)
                *reinterpret_cast<float4*>(&sm[ob + q4 * 4]) =
                    make_float4(acc[q4 * 4], acc[q4 * 4 + 1], acc[q4 * 4 + 2], acc[q4 * 4 + 3]);
        }
    }
    __syncthreads();

    // ---------------- Phase 3: E = exp(scale * k1 . k2)  (+ stage Wp over dead Wk)
    for (int idx = tid; idx < 64 * 64; idx += BDIM) {
        int r = idx >> 6, c = idx & 63;
        sm[oWk + r * 68 + c] = Wp[idx];     // Wp[c][i] at stride 68 (broadcast reads only)
    }
    const float SCALE = 0.17677669529663687f;   // 1/sqrt(32)
    // 26 warp-tasks: (n, xg) with 4 x-rows each; lanes = y (two halves).
    for (int t = wid; t < 26; t += 16) {
        int n = t / 13, xg = t % 13;
        int x0 = xg * 4;
        float acc[4][2] = {};
        int k1b = oK + x0 * 65 + n * 32;
        int k2b = oK + 49 * 65 + n * 32;
        bool has1 = (lane < 17);
#pragma unroll 8
        for (int c = 0; c < 32; c++) {
            float e0 = sm[k2b + lane * 65 + c];                       // conflict-free
            float e1 = has1 ? sm[k2b + (lane + 32) * 65 + c] : 0.f;
#pragma unroll
            for (int xx = 0; xx < 4; xx++) {
                float k1v = sm[k1b + xx * 65 + c];                    // broadcast
                acc[xx][0] += k1v * e0;
                acc[xx][1] += k1v * e1;
            }
        }
#pragma unroll
        for (int xx = 0; xx < 4; xx++) {
            int x = x0 + xx;
            if (x < 49) {
                int eb = oE + (n * 49 + x) * 53;
                sm[eb + lane] = __expf(acc[xx][0] * SCALE);           // lanes contiguous
                if (has1) sm[eb + lane + 32] = __expf(acc[xx][1] * SCALE);
            }
        }
    }
    __syncthreads();

    // ---------------- Phase 4: reciprocal column / row sums ----------------
    for (int idx = tid; idx < 196; idx += BDIM) {
        int half = idx / 98;
        int r = idx % 98;
        int n = r / 49, q = r % 49;
        float ssum = 0.f;
        if (half == 0) {  // colsum over x at y=q (lanes read stride-1)
#pragma unroll 7
            for (int x = 0; x < 49; x++) ssum += sm[oE + (n * 49 + x) * 53 + q];
            sm[oCS + r] = 1.f / ssum;
        } else {          // rowsum over y at x=q (lane stride 53: conflict-free)
#pragma unroll 7
            for (int y = 0; y < 49; y++) ssum += sm[oE + (n * 49 + q) * 53 + y];
            sm[oRS + r] = 1.f / ssum;
        }
    }
    __syncthreads();

    // ---------------- Phase 5: o1 / o2 -> OT[i][p] (channel-major, stride 53)
    // 16 warp-tasks = (which, n, dg): 4 output channels x all pixels per task.
    {
        int t = wid;                 // exactly one task per warp
        int which = t >> 3;
        int n  = (t >> 2) & 1;
        int dg = t & 3;
        bool has1 = (lane < 17);
        float acc[4][2] = {};
        if (which == 0) {
            // o1[d][y] = (1/colsum[y]) * sum_x E[x][y] * v1[x][d]; lanes = y
            int vb = oV + n * 16 + dg * 4;
#pragma unroll 7
            for (int x = 0; x < 49; x++) {
                float4 v4 = *reinterpret_cast<const float4*>(&sm[vb + x * 36]);  // broadcast
                int eb = oE + (n * 49 + x) * 53;
                float e0 = sm[eb + lane];
                float e1 = has1 ? sm[eb + lane + 32] : 0.f;
                acc[0][0] += e0 * v4.x; acc[1][0] += e0 * v4.y; acc[2][0] += e0 * v4.z; acc[3][0] += e0 * v4.w;
                acc[0][1] += e1 * v4.x; acc[1][1] += e1 * v4.y; acc[2][1] += e1 * v4.z; acc[3][1] += e1 * v4.w;
            }
            float f0 = sm[oCS + n * 49 + lane];
            float f1 = has1 ? sm[oCS + n * 49 + lane + 32] : 0.f;
            int ib = n * 16 + dg * 4;
#pragma unroll
            for (int j = 0; j < 4; j++) {
                sm[oOT + (ib + j) * 53 + lane] = acc[j][0] * f0;
                if (has1) sm[oOT + (ib + j) * 53 + lane + 32] = acc[j][1] * f1;
            }
        } else {
            // o2[d][x] = (1/rowsum[x]) * sum_y E[x][y] * v2[y][d]; lanes = x
            int vb = oV + 49 * 36 + n * 16 + dg * 4;
            int eb0 = oE + (n * 49 + lane) * 53;
            int eb1 = oE + (n * 49 + lane + 32) * 53;
#pragma unroll 7
            for (int y = 0; y < 49; y++) {
                float4 v4 = *reinterpret_cast<const float4*>(&sm[vb + y * 36]);  // broadcast
                float e0 = sm[eb0 + y];                   // lane stride 53: conflict-free
                float e1 = has1 ? sm[eb1 + y] : 0.f;
                acc[0][0] += e0 * v4.x; acc[1][0] += e0 * v4.y; acc[2][0] += e0 * v4.z; acc[3][0] += e0 * v4.w;
                acc[0][1] += e1 * v4.x; acc[1][1] += e1 * v4.y; acc[2][1] += e1 * v4.z; acc[3][1] += e1 * v4.w;
            }
            float f0 = sm[oRS + n * 49 + lane];
            float f1 = has1 ? sm[oRS + n * 49 + lane + 32] : 0.f;
            int ib = 32 + n * 16 + dg * 4;
#pragma unroll
            for (int j = 0; j < 4; j++) {
                sm[oOT + (ib + j) * 53 + lane] = acc[j][0] * f0;
                if (has1) sm[oOT + (ib + j) * 53 + lane + 32] = acc[j][1] * f1;
            }
        }
    }
    __syncthreads();

    // ---------------- Phase 6: Out[c][p] = bp[c] + sum_i OT[i][p] * Wp[c][i]
    // 16 warp-tasks: 4 channels each; lanes = p (two halves).
    {
        int cg = wid;                    // 0..15
        int c0 = cg * 4;
        bool has1 = (lane < 17);
        float acc[4][2];
#pragma unroll
        for (int j = 0; j < 4; j++) { acc[j][0] = sm[obp + c0 + j]; acc[j][1] = acc[j][0]; }
#pragma unroll 8
        for (int i = 0; i < 64; i++) {
            float o0 = sm[oOT + i * 53 + lane];
            float o1v = has1 ? sm[oOT + i * 53 + lane + 32] : 0.f;
#pragma unroll
            for (int j = 0; j < 4; j++) {
                float w = sm[oWk + (c0 + j) * 68 + i];     // Wp (broadcast)
                acc[j][0] += w * o0;
                acc[j][1] += w * o1v;
            }
        }
#pragma unroll
        for (int j = 0; j < 4; j++) {
            sm[oOut + (c0 + j) * 49 + lane] = acc[j][0];
            if (has1) sm[oOut + (c0 + j) * 49 + lane + 32] = acc[j][1];
        }
    }
    __syncthreads();

    // ---------------- Phase 7: scatter stores ----------------
    for (int idx = tid; idx < 64 * 49; idx += BDIM) {
        int c = idx / 49;
        int p = idx % 49;
        int px = p / 7, py = p % 7;
        int h = si * 21 + px * 4, w = sj * 21 + py * 4;
        out[((b * 64 + c) * 256 + h) * 256 + w] = sm[oOut + idx];
    }
}

extern "C" void kernel_launch(void* const* d_in, const int* in_sizes, int n_in,
                              void* d_out, int out_size) {
    const float* x1 = (const float*)d_in[0];
    const float* x2 = (const float*)d_in[1];
    const float* Wk = (const float*)d_in[2];
    const float* bk = (const float*)d_in[3];
    const float* Wv = (const float*)d_in[4];
    const float* bv = (const float*)d_in[5];
    const float* Wp = (const float*)d_in[6];
    const float* bp = (const float*)d_in[7];
    float* out = (float*)d_out;

    fill_bias_kernel<<<32768, 256>>>(out, bp);

    cudaFuncSetAttribute(attn_patch_kernel,
                         cudaFuncAttributeMaxDynamicSharedMemorySize, SMEM_BYTES);
    attn_patch_kernel<<<1152, BDIM, SMEM_BYTES>>>(x1, x2, Wk, bk, Wv, bv, Wp, bp, out);
}

// round 3
// speedup vs baseline: 1.7677x; 1.2611x over previous
#include <cuda_runtime.h>

// ---------------------------------------------------------------------------
// B=8, H=W=256, I_DIM=64, K_DIM=64/stream, V_DIM=32/stream, NH=2 (hd_k=32, hd_v=16)
// unfold(256, P=7, NK=4) -> p=7, stride=21, dilation=4, nk=12
// => 144 patches of 49 px; positions {21i+4j} all distinct per dim
// => fold has no overlap; attn writes exactly Sh x Sw, fill writes the rest.
// ---------------------------------------------------------------------------

#define BDIM 512           // 16 warps
#define N_ATTN 1152        // 8 batches * 144 patches
#define N_FILL 2048        // fill blocks (8 float4 per thread)

// ---- smem layout (float offsets); weights live in global/L1 now ----
constexpr int oX   = 0;                 // X[(st*49+p)*68 + c]   (float4 rows)
constexpr int oE   = 0;                 // alias: E[(n*49+x)*53 + y]
constexpr int oOut = 0;                 // alias: Out[c*49 + p]  (phase 6+)
constexpr int oK   = 6664;              // K[(st*49+p)*65 + c]
constexpr int oOT  = 6664;              // alias: OT[i*53 + p]   (phase 5+)
constexpr int oV   = 13036;             // V[(st*49+p)*36 + d]   (float4, aligned)
constexpr int oCS  = oV + 3528;         // 16564 : 98 (1/colsum)
constexpr int oRS  = oCS + 98;          // 16662 : 98 (1/rowsum)
constexpr int SMEMF = oRS + 98;         // 16760 floats
constexpr int SMEM_BYTES = SMEMF * 4;   // 67040 bytes -> 2 CTAs/SM

// v in [0,256) is a sampled coordinate iff v = 21*i + 4*j, i<12, j<7.
// Since 21 = 1 (mod 4), the only candidate i's are v mod 4 (+4, +8).
__device__ __forceinline__ bool is_sampled(int v) {
    int i = v & 3;
#pragma unroll
    for (int t = 0; t < 3; t++, i += 4) {
        int d = v - 21 * i;
        if (i < 12 && d >= 0 && d <= 24) return true;
    }
    return false;
}

__global__ void __launch_bounds__(BDIM, 2)
fused_kernel(const float* __restrict__ x1, const float* __restrict__ x2,
             const float* __restrict__ Wk, const float* __restrict__ bk,
             const float* __restrict__ Wv, const float* __restrict__ bv,
             const float* __restrict__ Wp, const float* __restrict__ bp,
             float* __restrict__ out) {
    // ======================= FILL PATH (blocks >= N_ATTN) ===================
    if (blockIdx.x >= N_ATTN) {
        unsigned g = (blockIdx.x - N_ATTN) * BDIM + threadIdx.x;   // < 1048576
#pragma unroll
        for (int k = 0; k < 8; k++) {
            unsigned i = g + k * (N_FILL * BDIM);                  // < 8388608 float4
            int w4 = (i & 63) << 2;
            int h  = (i >> 6) & 255;
            int c  = (i >> 14) & 63;
            float v = __ldg(&bp[c]);
            if (!is_sampled(h)) {
                reinterpret_cast<float4*>(out)[i] = make_float4(v, v, v, v);
            } else {
                float* o = out + (size_t)i * 4;
#pragma unroll
                for (int q = 0; q < 4; q++)
                    if (!is_sampled(w4 + q)) o[q] = v;
            }
        }
        return;
    }

    // ======================= ATTENTION PATH =================================
    extern __shared__ __align__(16) float sm[];
    const int tid  = threadIdx.x;
    const int lane = tid & 31;
    const int wid  = tid >> 5;

    const int b  = blockIdx.x / 144;
    const int s  = blockIdx.x % 144;
    const int si = s / 12, sj = s % 12;

    // ---- Phase 1: gather x1/x2 at the 49 patch pixels ----
    for (int idx = tid; idx < 2 * 64 * 49; idx += BDIM) {
        int st = idx / 3136;
        int r  = idx % 3136;
        int c  = r / 49;
        int p  = r % 49;
        int px = p / 7, py = p % 7;
        int h = si * 21 + px * 4, w = sj * 21 + py * 4;
        const float* xp = st ? x2 : x1;
        sm[oX + (st * 49 + p) * 68 + c] = __ldg(&xp[((b * 64 + c) * 256 + h) * 256 + w]);
    }
    __syncthreads();

    // ---- Phase 2: 1x1 convs -> K (2x49x64 @65), V (2x49x32 @36) ----
    // 48 warp-tasks (job 0..23, half 0..1): jobs 0-15 K (8 oc each), 16-23 V (8 oc each).
    for (int t = wid; t < 48; t += 16) {
        int job = t >> 1, half = t & 1;
        int p = lane + half * 32;
        bool act = (p < 49);
        int pc = act ? p : 0;
        int st, oc0;
        const float* Wg;
        const float* bg;
        if (job < 16) {
            st = job >> 3; oc0 = (job & 7) * 8;
            Wg = Wk + (st * 64 + oc0) * 64;  bg = bk + st * 64 + oc0;
        } else {
            int j2 = job - 16;
            st = j2 >> 2; oc0 = (j2 & 3) * 8;
            Wg = Wv + (st * 32 + oc0) * 64;  bg = bv + st * 32 + oc0;
        }
        float acc[8];
#pragma unroll
        for (int q = 0; q < 8; q++) acc[q] = __ldg(&bg[q]);
        const float4* xrow = reinterpret_cast<const float4*>(&sm[oX + (st * 49 + pc) * 68]);
        const float4* W4   = reinterpret_cast<const float4*>(Wg);
#pragma unroll
        for (int i4 = 0; i4 < 16; i4++) {
            float4 xv = xrow[i4];
#pragma unroll
            for (int q = 0; q < 8; q++) {
                float4 wv = __ldg(&W4[q * 16 + i4]);     // broadcast, L1-resident
                acc[q] += xv.x * wv.x + xv.y * wv.y + xv.z * wv.z + xv.w * wv.w;
            }
        }
        if (act) {
            if (job < 16) {
                int ob = oK + (st * 49 + p) * 65 + oc0;
#pragma unroll
                for (int q = 0; q < 8; q++) sm[ob + q] = acc[q];   // stride 65: conflict-free
            } else {
                int ob = oV + (st * 49 + p) * 36 + oc0;
                *reinterpret_cast<float4*>(&sm[ob])     = make_float4(acc[0], acc[1], acc[2], acc[3]);
                *reinterpret_cast<float4*>(&sm[ob + 4]) = make_float4(acc[4], acc[5], acc[6], acc[7]);
            }
        }
    }
    __syncthreads();

    // ---- Phase 3: E = exp(scale * k1 . k2) ----
    const float SCALE = 0.17677669529663687f;   // 1/sqrt(32)
    for (int t = wid; t < 26; t += 16) {
        int n = t / 13, xg = t % 13;
        int x0 = xg * 4;
        float acc[4][2] = {};
        int k1b = oK + x0 * 65 + n * 32;
        int k2b = oK + 49 * 65 + n * 32;
        bool has1 = (lane < 17);
#pragma unroll 8
        for (int c = 0; c < 32; c++) {
            float e0 = sm[k2b + lane * 65 + c];                     // conflict-free
            float e1 = has1 ? sm[k2b + (lane + 32) * 65 + c] : 0.f;
#pragma unroll
            for (int xx = 0; xx < 4; xx++) {
                float k1v = sm[k1b + xx * 65 + c];                  // broadcast
                acc[xx][0] += k1v * e0;
                acc[xx][1] += k1v * e1;
            }
        }
#pragma unroll
        for (int xx = 0; xx < 4; xx++) {
            int x = x0 + xx;
            if (x < 49) {
                int eb = oE + (n * 49 + x) * 53;
                sm[eb + lane] = __expf(acc[xx][0] * SCALE);
                if (has1) sm[eb + lane + 32] = __expf(acc[xx][1] * SCALE);
            }
        }
    }
    __syncthreads();

    // ---- Phase 4: reciprocal column / row sums ----
    for (int idx = tid; idx < 196; idx += BDIM) {
        int half = idx / 98;
        int r = idx % 98;
        int n = r / 49, q = r % 49;
        float ssum = 0.f;
        if (half == 0) {
#pragma unroll 7
            for (int x = 0; x < 49; x++) ssum += sm[oE + (n * 49 + x) * 53 + q];
            sm[oCS + r] = 1.f / ssum;
        } else {
#pragma unroll 7
            for (int y = 0; y < 49; y++) ssum += sm[oE + (n * 49 + q) * 53 + y];
            sm[oRS + r] = 1.f / ssum;
        }
    }
    __syncthreads();

    // ---- Phase 5: o1 / o2 -> OT[i][p] (channel-major, stride 53); 16 warp-tasks ----
    {
        int which = wid >> 3;
        int n  = (wid >> 2) & 1;
        int dg = wid & 3;
        bool has1 = (lane < 17);
        float acc[4][2] = {};
        if (which == 0) {
            // o1[d][y] = (1/colsum[y]) sum_x E[x][y] * v1[x][d]; lanes = y
            int vb = oV + n * 16 + dg * 4;
#pragma unroll 7
            for (int x = 0; x < 49; x++) {
                float4 v4 = *reinterpret_cast<const float4*>(&sm[vb + x * 36]);  // broadcast
                int eb = oE + (n * 49 + x) * 53;
                float e0 = sm[eb + lane];
                float e1 = has1 ? sm[eb + lane + 32] : 0.f;
                acc[0][0] += e0 * v4.x; acc[1][0] += e0 * v4.y; acc[2][0] += e0 * v4.z; acc[3][0] += e0 * v4.w;
                acc[0][1] += e1 * v4.x; acc[1][1] += e1 * v4.y; acc[2][1] += e1 * v4.z; acc[3][1] += e1 * v4.w;
            }
            float f0 = sm[oCS + n * 49 + lane];
            float f1 = has1 ? sm[oCS + n * 49 + lane + 32] : 0.f;
            int ib = n * 16 + dg * 4;
#pragma unroll
            for (int j = 0; j < 4; j++) {
                sm[oOT + (ib + j) * 53 + lane] = acc[j][0] * f0;
                if (has1) sm[oOT + (ib + j) * 53 + lane + 32] = acc[j][1] * f1;
            }
        } else {
            // o2[d][x] = (1/rowsum[x]) sum_y E[x][y] * v2[y][d]; lanes = x
            int vb = oV + 49 * 36 + n * 16 + dg * 4;
            int eb0 = oE + (n * 49 + lane) * 53;
            int eb1 = oE + (n * 49 + lane + 32) * 53;
#pragma unroll 7
            for (int y = 0; y < 49; y++) {
                float4 v4 = *reinterpret_cast<const float4*>(&sm[vb + y * 36]);  // broadcast
                float e0 = sm[eb0 + y];
                float e1 = has1 ? sm[eb1 + y] : 0.f;
                acc[0][0] += e0 * v4.x; acc[1][0] += e0 * v4.y; acc[2][0] += e0 * v4.z; acc[3][0] += e0 * v4.w;
                acc[0][1] += e1 * v4.x; acc[1][1] += e1 * v4.y; acc[2][1] += e1 * v4.z; acc[3][1] += e1 * v4.w;
            }
            float f0 = sm[oRS + n * 49 + lane];
            float f1 = has1 ? sm[oRS + n * 49 + lane + 32] : 0.f;
            int ib = 32 + n * 16 + dg * 4;
#pragma unroll
            for (int j = 0; j < 4; j++) {
                sm[oOT + (ib + j) * 53 + lane] = acc[j][0] * f0;
                if (has1) sm[oOT + (ib + j) * 53 + lane + 32] = acc[j][1] * f1;
            }
        }
    }
    __syncthreads();

    // ---- Phase 6: Out[c][p] = bp[c] + sum_i OT[i][p] * Wp[c][i]; 16 warp-tasks ----
    {
        int c0 = wid * 4;
        bool has1 = (lane < 17);
        float acc[4][2];
#pragma unroll
        for (int j = 0; j < 4; j++) { acc[j][0] = __ldg(&bp[c0 + j]); acc[j][1] = acc[j][0]; }
        const float4* Wp4 = reinterpret_cast<const float4*>(Wp);
#pragma unroll
        for (int i4 = 0; i4 < 16; i4++) {
            float o0[4], o1v[4];
#pragma unroll
            for (int k = 0; k < 4; k++) {
                o0[k]  = sm[oOT + (i4 * 4 + k) * 53 + lane];
                o1v[k] = has1 ? sm[oOT + (i4 * 4 + k) * 53 + lane + 32] : 0.f;
            }
#pragma unroll
            for (int j = 0; j < 4; j++) {
                float4 w4 = __ldg(&Wp4[(c0 + j) * 16 + i4]);   // broadcast
                acc[j][0] += w4.x * o0[0] + w4.y * o0[1] + w4.z * o0[2] + w4.w * o0[3];
                acc[j][1] += w4.x * o1v[0] + w4.y * o1v[1] + w4.z * o1v[2] + w4.w * o1v[3];
            }
        }
#pragma unroll
        for (int j = 0; j < 4; j++) {
            sm[oOut + (c0 + j) * 49 + lane] = acc[j][0];
            if (has1) sm[oOut + (c0 + j) * 49 + lane + 32] = acc[j][1];
        }
    }
    __syncthreads();

    // ---- Phase 7: scatter stores ----
    for (int idx = tid; idx < 64 * 49; idx += BDIM) {
        int c = idx / 49;
        int p = idx % 49;
        int px = p / 7, py = p % 7;
        int h = si * 21 + px * 4, w = sj * 21 + py * 4;
        out[((b * 64 + c) * 256 + h) * 256 + w] = sm[oOut + idx];
    }
}

extern "C" void kernel_launch(void* const* d_in, const int* in_sizes, int n_in,
                              void* d_out, int out_size) {
    const float* x1 = (const float*)d_in[0];
    const float* x2 = (const float*)d_in[1];
    const float* Wk = (const float*)d_in[2];
    const float* bk = (const float*)d_in[3];
    const float* Wv = (const float*)d_in[4];
    const float* bv = (const float*)d_in[5];
    const float* Wp = (const float*)d_in[6];
    const float* bp = (const float*)d_in[7];
    float* out = (float*)d_out;

    cudaFuncSetAttribute(fused_kernel,
                         cudaFuncAttributeMaxDynamicSharedMemorySize, SMEM_BYTES);
    fused_kernel<<<N_ATTN + N_FILL, BDIM, SMEM_BYTES>>>(x1, x2, Wk, bk, Wv, bv, Wp, bp, out);
}

// round 4
// speedup vs baseline: 2.0420x; 1.1552x over previous
#include <cuda_runtime.h>

// ---------------------------------------------------------------------------
// B=8, H=W=256, I_DIM=64, K_DIM=64/stream, V_DIM=32/stream, NH=2 (hd_k=32, hd_v=16)
// unfold(256, P=7, NK=4) -> p=7, stride=21, dilation=4, nk=12
// => 144 patches of 49 px; positions {21i+4j} all distinct per dim
// => fold has no overlap; attn writes exactly Sh x Sw, fill writes the rest.
// ---------------------------------------------------------------------------

#define BDIM 512           // 16 warps
#define N_ATTN 1152        // 8 batches * 144 patches
#define N_FILL 2048        // fill blocks (8 float4 per thread)

// ---- smem layout (float offsets); weights live in global/L1 ----
constexpr int oX   = 0;                 // X[(st*49+p)*68 + c]       (float4)
constexpr int oE   = 0;                 // alias: E[(n*49+x)*53 + y] (5194 <= 6664)
constexpr int oK   = 6664;              // K[(st*49+p)*68 + c]       (float4)
constexpr int oOT  = 6664;              // alias: OT[i*53 + p]       (3392)
constexpr int oOut = 6664 + 3392;       // alias: Out[c*49 + p]      (3136; 6528 <= 6664)
constexpr int oV   = 13328;             // V[(st*49+p)*36 + d]       (float4)
constexpr int oCS  = oV + 3528;         // 16856 : 98 (1/colsum)
constexpr int oRS  = oCS + 98;          // 16954 : 98 (1/rowsum)
constexpr int SMEMF = oRS + 98;         // 17052 floats
constexpr int SMEM_BYTES = SMEMF * 4;   // 68208 bytes -> 2 CTAs/SM

// v in [0,256) is sampled iff v = 21*i + 4*j, i<12, j<7. 21 ≡ 1 (mod 4).
__device__ __forceinline__ bool is_sampled(int v) {
    int i = v & 3;
#pragma unroll
    for (int t = 0; t < 3; t++, i += 4) {
        int d = v - 21 * i;
        if (i < 12 && d >= 0 && d <= 24) return true;
    }
    return false;
}

__global__ void __launch_bounds__(BDIM, 2)
fused_kernel(const float* __restrict__ x1, const float* __restrict__ x2,
             const float* __restrict__ Wk, const float* __restrict__ bk,
             const float* __restrict__ Wv, const float* __restrict__ bv,
             const float* __restrict__ Wp, const float* __restrict__ bp,
             float* __restrict__ out) {
    // ======================= FILL PATH (blocks >= N_ATTN) ===================
    if (blockIdx.x >= N_ATTN) {
        unsigned g = (blockIdx.x - N_ATTN) * BDIM + threadIdx.x;   // < 1048576
#pragma unroll
        for (int k = 0; k < 8; k++) {
            unsigned i = g + k * (N_FILL * BDIM);                  // < 8388608 float4
            int w4 = (i & 63) << 2;
            int h  = (i >> 6) & 255;
            int c  = (i >> 14) & 63;
            float v = __ldg(&bp[c]);
            if (!is_sampled(h)) {
                reinterpret_cast<float4*>(out)[i] = make_float4(v, v, v, v);
            } else {
                float* o = out + (size_t)i * 4;
#pragma unroll
                for (int q = 0; q < 4; q++)
                    if (!is_sampled(w4 + q)) o[q] = v;
            }
        }
        return;
    }

    // ======================= ATTENTION PATH =================================
    extern __shared__ __align__(16) float sm[];
    const int tid  = threadIdx.x;
    const int lane = tid & 31;
    const int wid  = tid >> 5;
    const bool has1 = (lane < 17);          // second pixel half p = lane+32 <= 48

    const int b  = blockIdx.x / 144;
    const int s  = blockIdx.x % 144;
    const int si = s / 12, sj = s % 12;

    // ---- Phase 1: gather x1/x2 at the 49 patch pixels ----
    for (int idx = tid; idx < 2 * 64 * 49; idx += BDIM) {
        int st = idx / 3136;
        int r  = idx % 3136;
        int c  = r / 49;
        int p  = r % 49;
        int px = p / 7, py = p % 7;
        int h = si * 21 + px * 4, w = sj * 21 + py * 4;
        const float* xp = st ? x2 : x1;
        sm[oX + (st * 49 + p) * 68 + c] = __ldg(&xp[((b * 64 + c) * 256 + h) * 256 + w]);
    }
    __syncthreads();

    // ---- Phase 2: 1x1 convs. 16 warp-tasks, both pixel halves per task. ----
    // wid 0-7 : K, st=wid>>2, 16 oc   -> K[(st*49+p)*68 + oc]
    // wid 8-15: V, st=(wid-8)>>2, 8 oc -> V[(st*49+p)*36 + oc]
    if (wid < 8) {
        int st  = wid >> 2;
        int oc0 = (wid & 3) * 16;
        const float4* W4 = reinterpret_cast<const float4*>(Wk + (st * 64 + oc0) * 64);
        float acc[16][2];
#pragma unroll
        for (int q = 0; q < 16; q++) { acc[q][0] = __ldg(&bk[st * 64 + oc0 + q]); acc[q][1] = acc[q][0]; }
        const float4* xa = reinterpret_cast<const float4*>(&sm[oX + (st * 49 + lane) * 68]);
        const float4* xb = reinterpret_cast<const float4*>(&sm[oX + (st * 49 + lane + 32) * 68]);
#pragma unroll
        for (int i4 = 0; i4 < 16; i4++) {
            float4 a = xa[i4];
            float4 bx = has1 ? xb[i4] : make_float4(0.f, 0.f, 0.f, 0.f);
#pragma unroll
            for (int q = 0; q < 16; q++) {
                float4 wv = __ldg(&W4[q * 16 + i4]);          // broadcast, L1-resident
                acc[q][0] += a.x * wv.x + a.y * wv.y + a.z * wv.z + a.w * wv.w;
                acc[q][1] += bx.x * wv.x + bx.y * wv.y + bx.z * wv.z + bx.w * wv.w;
            }
        }
        int ob0 = oK + (st * 49 + lane) * 68 + oc0;
        int ob1 = oK + (st * 49 + lane + 32) * 68 + oc0;
#pragma unroll
        for (int q4 = 0; q4 < 4; q4++) {
            *reinterpret_cast<float4*>(&sm[ob0 + q4 * 4]) =
                make_float4(acc[q4 * 4][0], acc[q4 * 4 + 1][0], acc[q4 * 4 + 2][0], acc[q4 * 4 + 3][0]);
            if (has1)
                *reinterpret_cast<float4*>(&sm[ob1 + q4 * 4]) =
                    make_float4(acc[q4 * 4][1], acc[q4 * 4 + 1][1], acc[q4 * 4 + 2][1], acc[q4 * 4 + 3][1]);
        }
    } else {
        int v2  = wid - 8;
        int st  = v2 >> 2;
        int oc0 = (v2 & 3) * 8;
        const float4* W4 = reinterpret_cast<const float4*>(Wv + (st * 32 + oc0) * 64);
        float acc[8][2];
#pragma unroll
        for (int q = 0; q < 8; q++) { acc[q][0] = __ldg(&bv[st * 32 + oc0 + q]); acc[q][1] = acc[q][0]; }
        const float4* xa = reinterpret_cast<const float4*>(&sm[oX + (st * 49 + lane) * 68]);
        const float4* xb = reinterpret_cast<const float4*>(&sm[oX + (st * 49 + lane + 32) * 68]);
#pragma unroll
        for (int i4 = 0; i4 < 16; i4++) {
            float4 a = xa[i4];
            float4 bx = has1 ? xb[i4] : make_float4(0.f, 0.f, 0.f, 0.f);
#pragma unroll
            for (int q = 0; q < 8; q++) {
                float4 wv = __ldg(&W4[q * 16 + i4]);
                acc[q][0] += a.x * wv.x + a.y * wv.y + a.z * wv.z + a.w * wv.w;
                acc[q][1] += bx.x * wv.x + bx.y * wv.y + bx.z * wv.z + bx.w * wv.w;
            }
        }
        int ob0 = oV + (st * 49 + lane) * 36 + oc0;
        int ob1 = oV + (st * 49 + lane + 32) * 36 + oc0;
#pragma unroll
        for (int q4 = 0; q4 < 2; q4++) {
            *reinterpret_cast<float4*>(&sm[ob0 + q4 * 4]) =
                make_float4(acc[q4 * 4][0], acc[q4 * 4 + 1][0], acc[q4 * 4 + 2][0], acc[q4 * 4 + 3][0]);
            if (has1)
                *reinterpret_cast<float4*>(&sm[ob1 + q4 * 4]) =
                    make_float4(acc[q4 * 4][1], acc[q4 * 4 + 1][1], acc[q4 * 4 + 2][1], acc[q4 * 4 + 3][1]);
        }
    }
    __syncthreads();

    // ---- Phase 3: E = exp(scale * k1 . k2); float4 on both operands ----
    const float SCALE = 0.17677669529663687f;   // 1/sqrt(32)
    for (int t = wid; t < 26; t += 16) {
        int n = t / 13, xg = t % 13;
        int x0 = xg * 4;
        float acc[4][2] = {};
        const float4* k2a = reinterpret_cast<const float4*>(&sm[oK + (49 + lane) * 68 + n * 32]);
        const float4* k2b = reinterpret_cast<const float4*>(&sm[oK + (49 + lane + 32) * 68 + n * 32]);
#pragma unroll
        for (int c4 = 0; c4 < 8; c4++) {
            float4 e0 = k2a[c4];                                        // conflict-free .128
            float4 e1 = has1 ? k2b[c4] : make_float4(0.f, 0.f, 0.f, 0.f);
#pragma unroll
            for (int xx = 0; xx < 4; xx++) {
                float4 k1 = *reinterpret_cast<const float4*>(
                    &sm[oK + (x0 + xx) * 68 + n * 32 + c4 * 4]);        // broadcast
                acc[xx][0] += k1.x * e0.x + k1.y * e0.y + k1.z * e0.z + k1.w * e0.w;
                acc[xx][1] += k1.x * e1.x + k1.y * e1.y + k1.z * e1.z + k1.w * e1.w;
            }
        }
#pragma unroll
        for (int xx = 0; xx < 4; xx++) {
            int x = x0 + xx;
            if (x < 49) {
                int eb = oE + (n * 49 + x) * 53;
                sm[eb + lane] = __expf(acc[xx][0] * SCALE);
                if (has1) sm[eb + lane + 32] = __expf(acc[xx][1] * SCALE);
            }
        }
    }
    __syncthreads();

    // ---- Phase 4: reciprocal column / row sums ----
    for (int idx = tid; idx < 196; idx += BDIM) {
        int half = idx / 98;
        int r = idx % 98;
        int n = r / 49, q = r % 49;
        float ssum = 0.f;
        if (half == 0) {
#pragma unroll 7
            for (int x = 0; x < 49; x++) ssum += sm[oE + (n * 49 + x) * 53 + q];
            sm[oCS + r] = 1.f / ssum;
        } else {
#pragma unroll 7
            for (int y = 0; y < 49; y++) ssum += sm[oE + (n * 49 + q) * 53 + y];
            sm[oRS + r] = 1.f / ssum;
        }
    }
    __syncthreads();

    // ---- Phase 5: o1 / o2 -> OT[i][p] (channel-major, stride 53); 16 warp-tasks ----
    {
        int which = wid >> 3;
        int n  = (wid >> 2) & 1;
        int dg = wid & 3;
        float acc[4][2] = {};
        if (which == 0) {
            // o1[d][y] = (1/colsum[y]) sum_x E[x][y] * v1[x][d]; lanes = y
            int vb = oV + n * 16 + dg * 4;
#pragma unroll 7
            for (int x = 0; x < 49; x++) {
                float4 v4 = *reinterpret_cast<const float4*>(&sm[vb + x * 36]);  // broadcast
                int eb = oE + (n * 49 + x) * 53;
                float e0 = sm[eb + lane];
                float e1 = has1 ? sm[eb + lane + 32] : 0.f;
                acc[0][0] += e0 * v4.x; acc[1][0] += e0 * v4.y; acc[2][0] += e0 * v4.z; acc[3][0] += e0 * v4.w;
                acc[0][1] += e1 * v4.x; acc[1][1] += e1 * v4.y; acc[2][1] += e1 * v4.z; acc[3][1] += e1 * v4.w;
            }
            float f0 = sm[oCS + n * 49 + lane];
            float f1 = has1 ? sm[oCS + n * 49 + lane + 32] : 0.f;
            int ib = n * 16 + dg * 4;
#pragma unroll
            for (int j = 0; j < 4; j++) {
                sm[oOT + (ib + j) * 53 + lane] = acc[j][0] * f0;
                if (has1) sm[oOT + (ib + j) * 53 + lane + 32] = acc[j][1] * f1;
            }
        } else {
            // o2[d][x] = (1/rowsum[x]) sum_y E[x][y] * v2[y][d]; lanes = x
            int vb = oV + 49 * 36 + n * 16 + dg * 4;
            int eb0 = oE + (n * 49 + lane) * 53;
            int eb1 = oE + (n * 49 + lane + 32) * 53;
#pragma unroll 7
            for (int y = 0; y < 49; y++) {
                float4 v4 = *reinterpret_cast<const float4*>(&sm[vb + y * 36]);  // broadcast
                float e0 = sm[eb0 + y];
                float e1 = has1 ? sm[eb1 + y] : 0.f;
                acc[0][0] += e0 * v4.x; acc[1][0] += e0 * v4.y; acc[2][0] += e0 * v4.z; acc[3][0] += e0 * v4.w;
                acc[0][1] += e1 * v4.x; acc[1][1] += e1 * v4.y; acc[2][1] += e1 * v4.z; acc[3][1] += e1 * v4.w;
            }
            float f0 = sm[oRS + n * 49 + lane];
            float f1 = has1 ? sm[oRS + n * 49 + lane + 32] : 0.f;
            int ib = 32 + n * 16 + dg * 4;
#pragma unroll
            for (int j = 0; j < 4; j++) {
                sm[oOT + (ib + j) * 53 + lane] = acc[j][0] * f0;
                if (has1) sm[oOT + (ib + j) * 53 + lane + 32] = acc[j][1] * f1;
            }
        }
    }
    __syncthreads();

    // ---- Phase 6: Out[c][p] = bp[c] + sum_i OT[i][p] * Wp[c][i]; 16 warp-tasks ----
    {
        int c0 = wid * 4;
        float acc[4][2];
#pragma unroll
        for (int j = 0; j < 4; j++) { acc[j][0] = __ldg(&bp[c0 + j]); acc[j][1] = acc[j][0]; }
        const float4* Wp4 = reinterpret_cast<const float4*>(Wp);
#pragma unroll
        for (int i4 = 0; i4 < 16; i4++) {
            float o0[4], o1v[4];
#pragma unroll
            for (int k = 0; k < 4; k++) {
                o0[k]  = sm[oOT + (i4 * 4 + k) * 53 + lane];
                o1v[k] = has1 ? sm[oOT + (i4 * 4 + k) * 53 + lane + 32] : 0.f;
            }
#pragma unroll
            for (int j = 0; j < 4; j++) {
                float4 w4 = __ldg(&Wp4[(c0 + j) * 16 + i4]);   // broadcast
                acc[j][0] += w4.x * o0[0] + w4.y * o0[1] + w4.z * o0[2] + w4.w * o0[3];
                acc[j][1] += w4.x * o1v[0] + w4.y * o1v[1] + w4.z * o1v[2] + w4.w * o1v[3];
            }
        }
#pragma unroll
        for (int j = 0; j < 4; j++) {
            sm[oOut + (c0 + j) * 49 + lane] = acc[j][0];
            if (has1) sm[oOut + (c0 + j) * 49 + lane + 32] = acc[j][1];
        }
    }
    __syncthreads();

    // ---- Phase 7: scatter stores ----
    for (int idx = tid; idx < 64 * 49; idx += BDIM) {
        int c = idx / 49;
        int p = idx % 49;
        int px = p / 7, py = p % 7;
        int h = si * 21 + px * 4, w = sj * 21 + py * 4;
        out[((b * 64 + c) * 256 + h) * 256 + w] = sm[oOut + idx];
    }
}

extern "C" void kernel_launch(void* const* d_in, const int* in_sizes, int n_in,
                              void* d_out, int out_size) {
    const float* x1 = (const float*)d_in[0];
    const float* x2 = (const float*)d_in[1];
    const float* Wk = (const float*)d_in[2];
    const float* bk = (const float*)d_in[3];
    const float* Wv = (const float*)d_in[4];
    const float* bv = (const float*)d_in[5];
    const float* Wp = (const float*)d_in[6];
    const float* bp = (const float*)d_in[7];
    float* out = (float*)d_out;

    cudaFuncSetAttribute(fused_kernel,
                         cudaFuncAttributeMaxDynamicSharedMemorySize, SMEM_BYTES);
    fused_kernel<<<N_ATTN + N_FILL, BDIM, SMEM_BYTES>>>(x1, x2, Wk, bk, Wv, bv, Wp, bp, out);
}

// round 5
// speedup vs baseline: 2.0434x; 1.0007x over previous
#include <cuda_runtime.h>

// ---------------------------------------------------------------------------
// B=8, H=W=256, I_DIM=64, K_DIM=64/stream, V_DIM=32/stream, NH=2 (hd_k=32, hd_v=16)
// unfold(256, P=7, NK=4) -> p=7, stride=21, dilation=4, nk=12
// => 144 patches of 49 px; positions {21i+4j} all distinct per dim
// => fold has no overlap; attn writes exactly Sh x Sw, fill writes the rest.
// ---------------------------------------------------------------------------

#define BDIM 512           // 16 warps
#define N_ATTN 1152        // 8 batches * 144 patches
#define N_FILL 2048        // fill blocks (8 float4 per thread)

// ---- smem layout (float offsets); weights live in global/L1 ----
// Region A: X (2*49*68=6664) -> aliased by E (98x52=5096) + ET (98x52=5096)
constexpr int oX   = 0;
constexpr int oE   = 0;                  // E[(n*49+x)*52 + y]
constexpr int oET  = 5096;               // ET[(n*49+y)*52 + x]
constexpr int oA_SZ = 10192;
// Region B: K (98x68=6664) -> aliased by OT (49x68=3332) + Out (64x49=3136)
constexpr int oK   = oA_SZ;              // K[(st*49+p)*68 + c]
constexpr int oOT  = oA_SZ;              // OT[p*68 + i]
constexpr int oOut = oA_SZ + 3332;       // Out[c*49 + p]
constexpr int oV   = oA_SZ + 6664;       // 16856 : V[(st*49+p)*36 + d], 98 rows + 4 pad rows
constexpr int oCS  = oV + 102 * 36;      // 20528 : 98 (1/colsum)
constexpr int oRS  = oCS + 98;           // 20626 : 98 (1/rowsum)
constexpr int SMEMF = oRS + 98;          // 20724 floats
constexpr int SMEM_BYTES = SMEMF * 4;    // 82896 bytes -> 2 CTAs/SM

// v in [0,256) is sampled iff v = 21*i + 4*j, i<12, j<7. 21 ≡ 1 (mod 4).
__device__ __forceinline__ bool is_sampled(int v) {
    int i = v & 3;
#pragma unroll
    for (int t = 0; t < 3; t++, i += 4) {
        int d = v - 21 * i;
        if (i < 12 && d >= 0 && d <= 24) return true;
    }
    return false;
}

__global__ void __launch_bounds__(BDIM, 2)
fused_kernel(const float* __restrict__ x1, const float* __restrict__ x2,
             const float* __restrict__ Wk, const float* __restrict__ bk,
             const float* __restrict__ Wv, const float* __restrict__ bv,
             const float* __restrict__ Wp, const float* __restrict__ bp,
             float* __restrict__ out) {
    // ======================= FILL PATH (blocks >= N_ATTN) ===================
    if (blockIdx.x >= N_ATTN) {
        unsigned g = (blockIdx.x - N_ATTN) * BDIM + threadIdx.x;
#pragma unroll
        for (int k = 0; k < 8; k++) {
            unsigned i = g + k * (N_FILL * BDIM);
            int w4 = (i & 63) << 2;
            int h  = (i >> 6) & 255;
            int c  = (i >> 14) & 63;
            float v = __ldg(&bp[c]);
            if (!is_sampled(h)) {
                reinterpret_cast<float4*>(out)[i] = make_float4(v, v, v, v);
            } else {
                float* o = out + (size_t)i * 4;
#pragma unroll
                for (int q = 0; q < 4; q++)
                    if (!is_sampled(w4 + q)) o[q] = v;
            }
        }
        return;
    }

    // ======================= ATTENTION PATH =================================
    extern __shared__ __align__(16) float sm[];
    const int tid  = threadIdx.x;
    const int lane = tid & 31;
    const int wid  = tid >> 5;
    const bool has1 = (lane < 17);          // second pixel half p = lane+32 <= 48

    const int b  = blockIdx.x / 144;
    const int s  = blockIdx.x % 144;
    const int si = s / 12, sj = s % 12;

    // ---- Phase 1: gather x1/x2 at the 49 patch pixels ----
    for (int idx = tid; idx < 2 * 64 * 49; idx += BDIM) {
        int st = idx / 3136;
        int r  = idx % 3136;
        int c  = r / 49;
        int p  = r % 49;
        int px = p / 7, py = p % 7;
        int h = si * 21 + px * 4, w = sj * 21 + py * 4;
        const float* xp = st ? x2 : x1;
        sm[oX + (st * 49 + p) * 68 + c] = __ldg(&xp[((b * 64 + c) * 256 + h) * 256 + w]);
    }
    __syncthreads();

    // ---- Phase 2: 1x1 convs. 16 warp-tasks, both pixel halves per task. ----
    if (wid < 8) {
        int st  = wid >> 2;
        int oc0 = (wid & 3) * 16;
        const float4* W4 = reinterpret_cast<const float4*>(Wk + (st * 64 + oc0) * 64);
        float acc[16][2];
#pragma unroll
        for (int q = 0; q < 16; q++) { acc[q][0] = __ldg(&bk[st * 64 + oc0 + q]); acc[q][1] = acc[q][0]; }
        const float4* xa = reinterpret_cast<const float4*>(&sm[oX + (st * 49 + lane) * 68]);
        const float4* xb = reinterpret_cast<const float4*>(&sm[oX + (st * 49 + lane + 32) * 68]);
#pragma unroll
        for (int i4 = 0; i4 < 16; i4++) {
            float4 a = xa[i4];
            float4 bx = has1 ? xb[i4] : make_float4(0.f, 0.f, 0.f, 0.f);
#pragma unroll
            for (int q = 0; q < 16; q++) {
                float4 wv = __ldg(&W4[q * 16 + i4]);          // broadcast, L1-resident
                acc[q][0] += a.x * wv.x + a.y * wv.y + a.z * wv.z + a.w * wv.w;
                acc[q][1] += bx.x * wv.x + bx.y * wv.y + bx.z * wv.z + bx.w * wv.w;
            }
        }
        int ob0 = oK + (st * 49 + lane) * 68 + oc0;
        int ob1 = oK + (st * 49 + lane + 32) * 68 + oc0;
#pragma unroll
        for (int q4 = 0; q4 < 4; q4++) {
            *reinterpret_cast<float4*>(&sm[ob0 + q4 * 4]) =
                make_float4(acc[q4 * 4][0], acc[q4 * 4 + 1][0], acc[q4 * 4 + 2][0], acc[q4 * 4 + 3][0]);
            if (has1)
                *reinterpret_cast<float4*>(&sm[ob1 + q4 * 4]) =
                    make_float4(acc[q4 * 4][1], acc[q4 * 4 + 1][1], acc[q4 * 4 + 2][1], acc[q4 * 4 + 3][1]);
        }
    } else {
        int v2  = wid - 8;
        int st  = v2 >> 2;
        int oc0 = (v2 & 3) * 8;
        const float4* W4 = reinterpret_cast<const float4*>(Wv + (st * 32 + oc0) * 64);
        float acc[8][2];
#pragma unroll
        for (int q = 0; q < 8; q++) { acc[q][0] = __ldg(&bv[st * 32 + oc0 + q]); acc[q][1] = acc[q][0]; }
        const float4* xa = reinterpret_cast<const float4*>(&sm[oX + (st * 49 + lane) * 68]);
        const float4* xb = reinterpret_cast<const float4*>(&sm[oX + (st * 49 + lane + 32) * 68]);
#pragma unroll
        for (int i4 = 0; i4 < 16; i4++) {
            float4 a = xa[i4];
            float4 bx = has1 ? xb[i4] : make_float4(0.f, 0.f, 0.f, 0.f);
#pragma unroll
            for (int q = 0; q < 8; q++) {
                float4 wv = __ldg(&W4[q * 16 + i4]);
                acc[q][0] += a.x * wv.x + a.y * wv.y + a.z * wv.z + a.w * wv.w;
                acc[q][1] += bx.x * wv.x + bx.y * wv.y + bx.z * wv.z + bx.w * wv.w;
            }
        }
        int ob0 = oV + (st * 49 + lane) * 36 + oc0;
        int ob1 = oV + (st * 49 + lane + 32) * 36 + oc0;
#pragma unroll
        for (int q4 = 0; q4 < 2; q4++) {
            *reinterpret_cast<float4*>(&sm[ob0 + q4 * 4]) =
                make_float4(acc[q4 * 4][0], acc[q4 * 4 + 1][0], acc[q4 * 4 + 2][0], acc[q4 * 4 + 3][0]);
            if (has1)
                *reinterpret_cast<float4*>(&sm[ob1 + q4 * 4]) =
                    make_float4(acc[q4 * 4][1], acc[q4 * 4 + 1][1], acc[q4 * 4 + 2][1], acc[q4 * 4 + 3][1]);
        }
    }
    __syncthreads();

    // ---- Phase 3a: zero padding (E/ET cols 49..51; V pad rows 98..101) ----
    // Required: P4/P5 read float4 spans up to col 51 / row 100; stale smem may
    // hold NaNs, and 0 * NaN = NaN. Zeros guarantee exact no-op contributions.
    for (int idx = tid; idx < 588; idx += BDIM) {
        int reg = idx / 294;                 // 0 = E, 1 = ET
        int r   = (idx % 294) / 3;
        int cc  = 49 + (idx % 3);
        sm[(reg ? oET : oE) + r * 52 + cc] = 0.f;
    }
    for (int idx = tid; idx < 4 * 36; idx += BDIM) sm[oV + 98 * 36 + idx] = 0.f;

    // ---- Phase 3b: E = exp(scale * k1 . k2), plus transposed copy ET ----
    const float SCALE = 0.17677669529663687f;   // 1/sqrt(32)
    for (int t = wid; t < 26; t += 16) {
        int n = t / 13, xg = t % 13;
        int x0 = xg * 4;
        float acc[4][2] = {};
        const float4* k2a = reinterpret_cast<const float4*>(&sm[oK + (49 + lane) * 68 + n * 32]);
        const float4* k2b = reinterpret_cast<const float4*>(&sm[oK + (49 + lane + 32) * 68 + n * 32]);
#pragma unroll
        for (int c4 = 0; c4 < 8; c4++) {
            float4 e0 = k2a[c4];
            float4 e1 = has1 ? k2b[c4] : make_float4(0.f, 0.f, 0.f, 0.f);
#pragma unroll
            for (int xx = 0; xx < 4; xx++) {
                float4 k1 = *reinterpret_cast<const float4*>(
                    &sm[oK + (x0 + xx) * 68 + n * 32 + c4 * 4]);        // broadcast
                acc[xx][0] += k1.x * e0.x + k1.y * e0.y + k1.z * e0.z + k1.w * e0.w;
                acc[xx][1] += k1.x * e1.x + k1.y * e1.y + k1.z * e1.z + k1.w * e1.w;
            }
        }
#pragma unroll
        for (int xx = 0; xx < 4; xx++) {
            int x = x0 + xx;
            if (x < 49) {
                float v0 = __expf(acc[xx][0] * SCALE);
                sm[oE + (n * 49 + x) * 52 + lane] = v0;
                sm[oET + (n * 49 + lane) * 52 + x] = v0;
                if (has1) {
                    float v1 = __expf(acc[xx][1] * SCALE);
                    sm[oE + (n * 49 + x) * 52 + lane + 32] = v1;
                    sm[oET + (n * 49 + lane + 32) * 52 + x] = v1;
                }
            }
        }
    }
    __syncthreads();

    // ---- Phase 4: reciprocal column / row sums (vectorized row reads) ----
    for (int idx = tid; idx < 196; idx += BDIM) {
        int half = idx / 98;                 // 0: colsum via ET rows; 1: rowsum via E rows
        int r = idx % 98;
        const float4* row = reinterpret_cast<const float4*>(&sm[(half ? oE : oET) + r * 52]);
        float ssum = 0.f;
#pragma unroll
        for (int j4 = 0; j4 < 13; j4++) {
            float4 e = row[j4];
            ssum += e.x + e.y + e.z + e.w;   // pad cols are zero
        }
        sm[(half ? oRS : oCS) + r] = 1.f / ssum;
    }
    __syncthreads();

    // ---- Phase 5: o1 / o2 -> OT[p][i] (pixel-major, stride 68); 16 warp-tasks ----
    {
        int which = wid >> 3;
        int n  = (wid >> 2) & 1;
        int dg = wid & 3;
        float acc[4][2] = {};
        // o1: rows of ET (lanes = y), v1 rows broadcast
        // o2: rows of E  (lanes = x), v2 rows broadcast
        int erow0 = (which ? oE : oET) + (n * 49 + lane) * 52;
        int erow1 = (which ? oE : oET) + (n * 49 + lane + 32) * 52;
        int vbase = oV + which * 49 * 36 + n * 16 + dg * 4;
#pragma unroll
        for (int k4 = 0; k4 < 13; k4++) {
            float4 e0 = *reinterpret_cast<const float4*>(&sm[erow0 + k4 * 4]);
            float4 e1 = has1 ? *reinterpret_cast<const float4*>(&sm[erow1 + k4 * 4])
                             : make_float4(0.f, 0.f, 0.f, 0.f);
            float4 v0 = *reinterpret_cast<const float4*>(&sm[vbase + (k4 * 4 + 0) * 36]);
            float4 v1 = *reinterpret_cast<const float4*>(&sm[vbase + (k4 * 4 + 1) * 36]);
            float4 v2 = *reinterpret_cast<const float4*>(&sm[vbase + (k4 * 4 + 2) * 36]);
            float4 v3 = *reinterpret_cast<const float4*>(&sm[vbase + (k4 * 4 + 3) * 36]);
            acc[0][0] += e0.x * v0.x + e0.y * v1.x + e0.z * v2.x + e0.w * v3.x;
            acc[1][0] += e0.x * v0.y + e0.y * v1.y + e0.z * v2.y + e0.w * v3.y;
            acc[2][0] += e0.x * v0.z + e0.y * v1.z + e0.z * v2.z + e0.w * v3.z;
            acc[3][0] += e0.x * v0.w + e0.y * v1.w + e0.z * v2.w + e0.w * v3.w;
            acc[0][1] += e1.x * v0.x + e1.y * v1.x + e1.z * v2.x + e1.w * v3.x;
            acc[1][1] += e1.x * v0.y + e1.y * v1.y + e1.z * v2.y + e1.w * v3.y;
            acc[2][1] += e1.x * v0.z + e1.y * v1.z + e1.z * v2.z + e1.w * v3.z;
            acc[3][1] += e1.x * v0.w + e1.y * v1.w + e1.z * v2.w + e1.w * v3.w;
        }
        int fbase = (which ? oRS : oCS) + n * 49;
        float f0 = sm[fbase + lane];
        float f1 = has1 ? sm[fbase + lane + 32] : 0.f;
        int col = which * 32 + n * 16 + dg * 4;
        *reinterpret_cast<float4*>(&sm[oOT + lane * 68 + col]) =
            make_float4(acc[0][0] * f0, acc[1][0] * f0, acc[2][0] * f0, acc[3][0] * f0);
        if (has1)
            *reinterpret_cast<float4*>(&sm[oOT + (lane + 32) * 68 + col]) =
                make_float4(acc[0][1] * f1, acc[1][1] * f1, acc[2][1] * f1, acc[3][1] * f1);
    }
    __syncthreads();

    // ---- Phase 6: Out[c][p] = bp[c] + sum_i OT[p][i] * Wp[c][i]; 16 warp-tasks ----
    {
        int c0 = wid * 4;
        float acc[4][2];
#pragma unroll
        for (int j = 0; j < 4; j++) { acc[j][0] = __ldg(&bp[c0 + j]); acc[j][1] = acc[j][0]; }
        const float4* Wp4 = reinterpret_cast<const float4*>(Wp);
#pragma unroll
        for (int i4 = 0; i4 < 16; i4++) {
            float4 oa = *reinterpret_cast<const float4*>(&sm[oOT + lane * 68 + i4 * 4]);
            float4 ob = has1 ? *reinterpret_cast<const float4*>(&sm[oOT + (lane + 32) * 68 + i4 * 4])
                             : make_float4(0.f, 0.f, 0.f, 0.f);
#pragma unroll
            for (int j = 0; j < 4; j++) {
                float4 w4 = __ldg(&Wp4[(c0 + j) * 16 + i4]);   // broadcast
                acc[j][0] += w4.x * oa.x + w4.y * oa.y + w4.z * oa.z + w4.w * oa.w;
                acc[j][1] += w4.x * ob.x + w4.y * ob.y + w4.z * ob.z + w4.w * ob.w;
            }
        }
#pragma unroll
        for (int j = 0; j < 4; j++) {
            sm[oOut + (c0 + j) * 49 + lane] = acc[j][0];
            if (has1) sm[oOut + (c0 + j) * 49 + lane + 32] = acc[j][1];
        }
    }
    __syncthreads();

    // ---- Phase 7: scatter stores ----
    for (int idx = tid; idx < 64 * 49; idx += BDIM) {
        int c = idx / 49;
        int p = idx % 49;
        int px = p / 7, py = p % 7;
        int h = si * 21 + px * 4, w = sj * 21 + py * 4;
        out[((b * 64 + c) * 256 + h) * 256 + w] = sm[oOut + idx];
    }
}

extern "C" void kernel_launch(void* const* d_in, const int* in_sizes, int n_in,
                              void* d_out, int out_size) {
    const float* x1 = (const float*)d_in[0];
    const float* x2 = (const float*)d_in[1];
    const float* Wk = (const float*)d_in[2];
    const float* bk = (const float*)d_in[3];
    const float* Wv = (const float*)d_in[4];
    const float* bv = (const float*)d_in[5];
    const float* Wp = (const float*)d_in[6];
    const float* bp = (const float*)d_in[7];
    float* out = (float*)d_out;

    cudaFuncSetAttribute(fused_kernel,
                         cudaFuncAttributeMaxDynamicSharedMemorySize, SMEM_BYTES);
    fused_kernel<<<N_ATTN + N_FILL, BDIM, SMEM_BYTES>>>(x1, x2, Wk, bk, Wv, bv, Wp, bp, out);
}

// round 6
// speedup vs baseline: 2.1312x; 1.0430x over previous
#include <cuda_runtime.h>

// ---------------------------------------------------------------------------
// B=8, H=W=256, I_DIM=64, K_DIM=64/stream, V_DIM=32/stream, NH=2 (hd_k=32, hd_v=16)
// unfold(256, P=7, NK=4) -> p=7, stride=21, dilation=4, nk=12
// => 144 patches of 49 px; positions {21i+4j} all distinct per dim
// => fold has no overlap; attn writes exactly Sh x Sw, fill writes the rest.
// f32x2: packed fp32 FMA (2 IEEE fp32 fma per instruction) via PTX fma.rn.f32x2.
// ---------------------------------------------------------------------------

#define BDIM 512           // 16 warps
#define N_ATTN 1152        // 8 batches * 144 patches
#define N_FILL 2048        // fill blocks (8 float4 per thread)

typedef unsigned long long u64;

#define FFMA2(acc, a, b) asm("fma.rn.f32x2 %0, %1, %2, %0;" : "+l"(acc) : "l"(a), "l"(b))
#define DUP2(d, v)       asm("mov.b64 %0, {%1, %1};"        : "=l"(d)   : "f"(v))
#define PACK2(d, lo, hi) asm("mov.b64 %0, {%1, %2};"        : "=l"(d)   : "f"(lo), "f"(hi))
#define UNPACK2(lo, hi, d) asm("mov.b64 {%0, %1}, %2;"      : "=f"(lo), "=f"(hi) : "l"(d))

// Packed weight-pair buffers (lo = even output channel, hi = odd).
__device__ __align__(16) u64 gWk2[2 * 32 * 64];   // (st*32 + qp)*64 + c
__device__ __align__(16) u64 gWv2[2 * 16 * 64];   // (st*16 + qp)*64 + c
__device__ __align__(16) u64 gWp2[32 * 64];       // cp*64 + i

__global__ void repack_kernel(const float* __restrict__ Wk, const float* __restrict__ Wv,
                              const float* __restrict__ Wp) {
    int t = blockIdx.x * blockDim.x + threadIdx.x;
    int nt = gridDim.x * blockDim.x;
    for (int i = t; i < 4096; i += nt) {            // Wk pairs
        int c = i & 63, qp = (i >> 6) & 31, st = i >> 11;
        u64 d; PACK2(d, Wk[(st * 64 + 2 * qp) * 64 + c], Wk[(st * 64 + 2 * qp + 1) * 64 + c]);
        gWk2[i] = d;
    }
    for (int i = t; i < 2048; i += nt) {            // Wv pairs
        int c = i & 63, qp = (i >> 6) & 15, st = i >> 10;
        u64 d; PACK2(d, Wv[(st * 32 + 2 * qp) * 64 + c], Wv[(st * 32 + 2 * qp + 1) * 64 + c]);
        gWv2[i] = d;
    }
    for (int i = t; i < 2048; i += nt) {            // Wp pairs
        int ic = i & 63, cp = i >> 6;
        u64 d; PACK2(d, Wp[(2 * cp) * 64 + ic], Wp[(2 * cp + 1) * 64 + ic]);
        gWp2[i] = d;
    }
}

// ---- smem layout (float offsets) ----
constexpr int oX   = 0;
constexpr int oE   = 0;                  // E[(n*49+x)*52 + y]
constexpr int oET  = 5096;               // ET[(n*49+y)*52 + x]
constexpr int oA_SZ = 10192;
constexpr int oK   = oA_SZ;              // K[(st*49+p)*68 + c]
constexpr int oOT  = oA_SZ;              // OT[p*68 + i]
constexpr int oOut = oA_SZ + 3332;       // Out[c*49 + p]
constexpr int oV   = oA_SZ + 6664;       // V[(st*49+p)*36 + d], 98 rows + 4 pad rows
constexpr int oCS  = oV + 102 * 36;      // 98 (1/colsum)
constexpr int oRS  = oCS + 98;           // 98 (1/rowsum)
constexpr int SMEMF = oRS + 98;
constexpr int SMEM_BYTES = SMEMF * 4;    // 82896 bytes -> 2 CTAs/SM

// v in [0,256) is sampled iff v = 21*i + 4*j, i<12, j<7. 21 ≡ 1 (mod 4).
__device__ __forceinline__ bool is_sampled(int v) {
    int i = v & 3;
#pragma unroll
    for (int t = 0; t < 3; t++, i += 4) {
        int d = v - 21 * i;
        if (i < 12 && d >= 0 && d <= 24) return true;
    }
    return false;
}

__global__ void __launch_bounds__(BDIM, 2)
fused_kernel(const float* __restrict__ x1, const float* __restrict__ x2,
             const float* __restrict__ Wk, const float* __restrict__ bk,
             const float* __restrict__ Wv, const float* __restrict__ bv,
             const float* __restrict__ Wp, const float* __restrict__ bp,
             float* __restrict__ out) {
    // ======================= FILL PATH ===================
    if (blockIdx.x >= N_ATTN) {
        unsigned g = (blockIdx.x - N_ATTN) * BDIM + threadIdx.x;
#pragma unroll
        for (int k = 0; k < 8; k++) {
            unsigned i = g + k * (N_FILL * BDIM);
            int w4 = (i & 63) << 2;
            int h  = (i >> 6) & 255;
            int c  = (i >> 14) & 63;
            float v = __ldg(&bp[c]);
            if (!is_sampled(h)) {
                reinterpret_cast<float4*>(out)[i] = make_float4(v, v, v, v);
            } else {
                float* o = out + (size_t)i * 4;
#pragma unroll
                for (int q = 0; q < 4; q++)
                    if (!is_sampled(w4 + q)) o[q] = v;
            }
        }
        return;
    }

    // ======================= ATTENTION PATH =================================
    extern __shared__ __align__(16) float sm[];
    const int tid  = threadIdx.x;
    const int lane = tid & 31;
    const int wid  = tid >> 5;
    const bool has1 = (lane < 17);

    const int b  = blockIdx.x / 144;
    const int s  = blockIdx.x % 144;
    const int si = s / 12, sj = s % 12;

    // ---- Phase 1: gather x1/x2 at the 49 patch pixels ----
    for (int idx = tid; idx < 2 * 64 * 49; idx += BDIM) {
        int st = idx / 3136;
        int r  = idx % 3136;
        int c  = r / 49;
        int p  = r % 49;
        int px = p / 7, py = p % 7;
        int h = si * 21 + px * 4, w = sj * 21 + py * 4;
        const float* xp = st ? x2 : x1;
        sm[oX + (st * 49 + p) * 68 + c] = __ldg(&xp[((b * 64 + c) * 256 + h) * 256 + w]);
    }
    __syncthreads();

    // ---- Phase 2: 1x1 convs with packed f32x2 FMA; 2 uniform tasks/warp ----
    // K subtask: st = wid>>3, 4 oc-pairs starting pp0 = (wid&7)*4  (oc 8)
    // V subtask: st = wid>>3, 2 oc-pairs starting vp0 = (wid&7)*2  (oc 4)
    {
        const int st  = wid >> 3;
        const int sub = wid & 7;
        const float4* xa = reinterpret_cast<const float4*>(&sm[oX + (st * 49 + lane) * 68]);
        const float4* xb = reinterpret_cast<const float4*>(&sm[oX + (st * 49 + lane + 32) * 68]);

        // --------- K subtask: 4 pairs ---------
        {
            int pp0 = sub * 4;
            const ulonglong2* W2 = reinterpret_cast<const ulonglong2*>(&gWk2[(st * 32 + pp0) * 64]);
            u64 acc[4][2];
#pragma unroll
            for (int qp = 0; qp < 4; qp++) {
                u64 bb; PACK2(bb, __ldg(&bk[st * 64 + 2 * (pp0 + qp)]),
                                  __ldg(&bk[st * 64 + 2 * (pp0 + qp) + 1]));
                acc[qp][0] = bb; acc[qp][1] = bb;
            }
#pragma unroll
            for (int i4 = 0; i4 < 16; i4++) {
                float4 a = xa[i4];
                float4 bx = has1 ? xb[i4] : make_float4(0.f, 0.f, 0.f, 0.f);
                u64 da[4], db[4];
                DUP2(da[0], a.x); DUP2(da[1], a.y); DUP2(da[2], a.z); DUP2(da[3], a.w);
                DUP2(db[0], bx.x); DUP2(db[1], bx.y); DUP2(db[2], bx.z); DUP2(db[3], bx.w);
#pragma unroll
                for (int qp = 0; qp < 4; qp++) {
                    ulonglong2 w01 = __ldg(&W2[qp * 32 + i4 * 2]);
                    ulonglong2 w23 = __ldg(&W2[qp * 32 + i4 * 2 + 1]);
                    FFMA2(acc[qp][0], w01.x, da[0]); FFMA2(acc[qp][0], w01.y, da[1]);
                    FFMA2(acc[qp][0], w23.x, da[2]); FFMA2(acc[qp][0], w23.y, da[3]);
                    FFMA2(acc[qp][1], w01.x, db[0]); FFMA2(acc[qp][1], w01.y, db[1]);
                    FFMA2(acc[qp][1], w23.x, db[2]); FFMA2(acc[qp][1], w23.y, db[3]);
                }
            }
            int oc0 = pp0 * 2;
            int ob0 = oK + (st * 49 + lane) * 68 + oc0;
            int ob1 = oK + (st * 49 + lane + 32) * 68 + oc0;
#pragma unroll
            for (int g = 0; g < 2; g++) {
                float q0, q1, q2, q3;
                UNPACK2(q0, q1, acc[2 * g][0]); UNPACK2(q2, q3, acc[2 * g + 1][0]);
                *reinterpret_cast<float4*>(&sm[ob0 + g * 4]) = make_float4(q0, q1, q2, q3);
                if (has1) {
                    UNPACK2(q0, q1, acc[2 * g][1]); UNPACK2(q2, q3, acc[2 * g + 1][1]);
                    *reinterpret_cast<float4*>(&sm[ob1 + g * 4]) = make_float4(q0, q1, q2, q3);
                }
            }
        }

        // --------- V subtask: 2 pairs ---------
        {
            int vp0 = sub * 2;
            const ulonglong2* W2 = reinterpret_cast<const ulonglong2*>(&gWv2[(st * 16 + vp0) * 64]);
            u64 acc[2][2];
#pragma unroll
            for (int qp = 0; qp < 2; qp++) {
                u64 bb; PACK2(bb, __ldg(&bv[st * 32 + 2 * (vp0 + qp)]),
                                  __ldg(&bv[st * 32 + 2 * (vp0 + qp) + 1]));
                acc[qp][0] = bb; acc[qp][1] = bb;
            }
#pragma unroll
            for (int i4 = 0; i4 < 16; i4++) {
                float4 a = xa[i4];
                float4 bx = has1 ? xb[i4] : make_float4(0.f, 0.f, 0.f, 0.f);
                u64 da[4], db[4];
                DUP2(da[0], a.x); DUP2(da[1], a.y); DUP2(da[2], a.z); DUP2(da[3], a.w);
                DUP2(db[0], bx.x); DUP2(db[1], bx.y); DUP2(db[2], bx.z); DUP2(db[3], bx.w);
#pragma unroll
                for (int qp = 0; qp < 2; qp++) {
                    ulonglong2 w01 = __ldg(&W2[qp * 32 + i4 * 2]);
                    ulonglong2 w23 = __ldg(&W2[qp * 32 + i4 * 2 + 1]);
                    FFMA2(acc[qp][0], w01.x, da[0]); FFMA2(acc[qp][0], w01.y, da[1]);
                    FFMA2(acc[qp][0], w23.x, da[2]); FFMA2(acc[qp][0], w23.y, da[3]);
                    FFMA2(acc[qp][1], w01.x, db[0]); FFMA2(acc[qp][1], w01.y, db[1]);
                    FFMA2(acc[qp][1], w23.x, db[2]); FFMA2(acc[qp][1], w23.y, db[3]);
                }
            }
            int oc0 = vp0 * 2;
            int ob0 = oV + (st * 49 + lane) * 36 + oc0;
            int ob1 = oV + (st * 49 + lane + 32) * 36 + oc0;
            float q0, q1, q2, q3;
            UNPACK2(q0, q1, acc[0][0]); UNPACK2(q2, q3, acc[1][0]);
            *reinterpret_cast<float4*>(&sm[ob0]) = make_float4(q0, q1, q2, q3);
            if (has1) {
                UNPACK2(q0, q1, acc[0][1]); UNPACK2(q2, q3, acc[1][1]);
                *reinterpret_cast<float4*>(&sm[ob1]) = make_float4(q0, q1, q2, q3);
            }
        }
    }
    __syncthreads();

    // ---- Phase 3a: zero padding (E/ET cols 49..51; V pad rows 98..101) ----
    for (int idx = tid; idx < 588; idx += BDIM) {
        int reg = idx / 294;
        int r   = (idx % 294) / 3;
        int cc  = 49 + (idx % 3);
        sm[(reg ? oET : oE) + r * 52 + cc] = 0.f;
    }
    for (int idx = tid; idx < 4 * 36; idx += BDIM) sm[oV + 98 * 36 + idx] = 0.f;

    // ---- Phase 3b: E = exp(scale * k1 . k2), plus transposed copy ET ----
    const float SCALE = 0.17677669529663687f;   // 1/sqrt(32)
    for (int t = wid; t < 26; t += 16) {
        int n = t / 13, xg = t % 13;
        int x0 = xg * 4;
        float acc[4][2] = {};
        const float4* k2a = reinterpret_cast<const float4*>(&sm[oK + (49 + lane) * 68 + n * 32]);
        const float4* k2b = reinterpret_cast<const float4*>(&sm[oK + (49 + lane + 32) * 68 + n * 32]);
#pragma unroll
        for (int c4 = 0; c4 < 8; c4++) {
            float4 e0 = k2a[c4];
            float4 e1 = has1 ? k2b[c4] : make_float4(0.f, 0.f, 0.f, 0.f);
#pragma unroll
            for (int xx = 0; xx < 4; xx++) {
                float4 k1 = *reinterpret_cast<const float4*>(
                    &sm[oK + (x0 + xx) * 68 + n * 32 + c4 * 4]);        // broadcast
                acc[xx][0] += k1.x * e0.x + k1.y * e0.y + k1.z * e0.z + k1.w * e0.w;
                acc[xx][1] += k1.x * e1.x + k1.y * e1.y + k1.z * e1.z + k1.w * e1.w;
            }
        }
#pragma unroll
        for (int xx = 0; xx < 4; xx++) {
            int x = x0 + xx;
            if (x < 49) {
                float v0 = __expf(acc[xx][0] * SCALE);
                sm[oE + (n * 49 + x) * 52 + lane] = v0;
                sm[oET + (n * 49 + lane) * 52 + x] = v0;
                if (has1) {
                    float v1 = __expf(acc[xx][1] * SCALE);
                    sm[oE + (n * 49 + x) * 52 + lane + 32] = v1;
                    sm[oET + (n * 49 + lane + 32) * 52 + x] = v1;
                }
            }
        }
    }
    __syncthreads();

    // ---- Phase 4: reciprocal column / row sums ----
    for (int idx = tid; idx < 196; idx += BDIM) {
        int half = idx / 98;
        int r = idx % 98;
        const float4* row = reinterpret_cast<const float4*>(&sm[(half ? oE : oET) + r * 52]);
        float ssum = 0.f;
#pragma unroll
        for (int j4 = 0; j4 < 13; j4++) {
            float4 e = row[j4];
            ssum += e.x + e.y + e.z + e.w;
        }
        sm[(half ? oRS : oCS) + r] = 1.f / ssum;
    }
    __syncthreads();

    // ---- Phase 5: o1 / o2 -> OT[p][i] via packed V pairs; 16 warp-tasks ----
    {
        int which = wid >> 3;
        int n  = (wid >> 2) & 1;
        int dg = wid & 3;
        u64 acc[2][2] = {{0ull, 0ull}, {0ull, 0ull}};
        int erow0 = (which ? oE : oET) + (n * 49 + lane) * 52;
        int erow1 = (which ? oE : oET) + (n * 49 + lane + 32) * 52;
        int vbase = oV + which * 49 * 36 + n * 16 + dg * 4;
#pragma unroll
        for (int k4 = 0; k4 < 13; k4++) {
            float4 e0 = *reinterpret_cast<const float4*>(&sm[erow0 + k4 * 4]);
            float4 e1 = has1 ? *reinterpret_cast<const float4*>(&sm[erow1 + k4 * 4])
                             : make_float4(0.f, 0.f, 0.f, 0.f);
            float ea[4] = {e0.x, e0.y, e0.z, e0.w};
            float eb[4] = {e1.x, e1.y, e1.z, e1.w};
#pragma unroll
            for (int k = 0; k < 4; k++) {
                ulonglong2 v2 = *reinterpret_cast<const ulonglong2*>(&sm[vbase + (k4 * 4 + k) * 36]);
                u64 d0, d1;
                DUP2(d0, ea[k]); DUP2(d1, eb[k]);
                FFMA2(acc[0][0], v2.x, d0); FFMA2(acc[1][0], v2.y, d0);
                FFMA2(acc[0][1], v2.x, d1); FFMA2(acc[1][1], v2.y, d1);
            }
        }
        int fbase = (which ? oRS : oCS) + n * 49;
        float f0 = sm[fbase + lane];
        float f1 = has1 ? sm[fbase + lane + 32] : 0.f;
        int col = which * 32 + n * 16 + dg * 4;
        float a0, a1, a2, a3;
        UNPACK2(a0, a1, acc[0][0]); UNPACK2(a2, a3, acc[1][0]);
        *reinterpret_cast<float4*>(&sm[oOT + lane * 68 + col]) =
            make_float4(a0 * f0, a1 * f0, a2 * f0, a3 * f0);
        if (has1) {
            UNPACK2(a0, a1, acc[0][1]); UNPACK2(a2, a3, acc[1][1]);
            *reinterpret_cast<float4*>(&sm[oOT + (lane + 32) * 68 + col]) =
                make_float4(a0 * f1, a1 * f1, a2 * f1, a3 * f1);
        }
    }
    __syncthreads();

    // ---- Phase 6: Out[c][p] = bp[c] + sum_i OT[p][i] * Wp[c][i]; packed Wp pairs ----
    {
        int c0 = wid * 4;
        int cp0 = wid * 2;
        u64 acc[2][2];
#pragma unroll
        for (int j = 0; j < 2; j++) {
            u64 bb; PACK2(bb, __ldg(&bp[c0 + 2 * j]), __ldg(&bp[c0 + 2 * j + 1]));
            acc[j][0] = bb; acc[j][1] = bb;
        }
        const ulonglong2* W2 = reinterpret_cast<const ulonglong2*>(&gWp2[cp0 * 64]);
#pragma unroll
        for (int i4 = 0; i4 < 16; i4++) {
            float4 oa = *reinterpret_cast<const float4*>(&sm[oOT + lane * 68 + i4 * 4]);
            float4 ob = has1 ? *reinterpret_cast<const float4*>(&sm[oOT + (lane + 32) * 68 + i4 * 4])
                             : make_float4(0.f, 0.f, 0.f, 0.f);
            u64 da[4], db[4];
            DUP2(da[0], oa.x); DUP2(da[1], oa.y); DUP2(da[2], oa.z); DUP2(da[3], oa.w);
            DUP2(db[0], ob.x); DUP2(db[1], ob.y); DUP2(db[2], ob.z); DUP2(db[3], ob.w);
#pragma unroll
            for (int j = 0; j < 2; j++) {
                ulonglong2 w01 = __ldg(&W2[j * 32 + i4 * 2]);
                ulonglong2 w23 = __ldg(&W2[j * 32 + i4 * 2 + 1]);
                FFMA2(acc[j][0], w01.x, da[0]); FFMA2(acc[j][0], w01.y, da[1]);
                FFMA2(acc[j][0], w23.x, da[2]); FFMA2(acc[j][0], w23.y, da[3]);
                FFMA2(acc[j][1], w01.x, db[0]); FFMA2(acc[j][1], w01.y, db[1]);
                FFMA2(acc[j][1], w23.x, db[2]); FFMA2(acc[j][1], w23.y, db[3]);
            }
        }
        float q0, q1, q2, q3;
        UNPACK2(q0, q1, acc[0][0]); UNPACK2(q2, q3, acc[1][0]);
        sm[oOut + (c0 + 0) * 49 + lane] = q0;
        sm[oOut + (c0 + 1) * 49 + lane] = q1;
        sm[oOut + (c0 + 2) * 49 + lane] = q2;
        sm[oOut + (c0 + 3) * 49 + lane] = q3;
        if (has1) {
            UNPACK2(q0, q1, acc[0][1]); UNPACK2(q2, q3, acc[1][1]);
            sm[oOut + (c0 + 0) * 49 + lane + 32] = q0;
            sm[oOut + (c0 + 1) * 49 + lane + 32] = q1;
            sm[oOut + (c0 + 2) * 49 + lane + 32] = q2;
            sm[oOut + (c0 + 3) * 49 + lane + 32] = q3;
        }
    }
    __syncthreads();

    // ---- Phase 7: scatter stores ----
    for (int idx = tid; idx < 64 * 49; idx += BDIM) {
        int c = idx / 49;
        int p = idx % 49;
        int px = p / 7, py = p % 7;
        int h = si * 21 + px * 4, w = sj * 21 + py * 4;
        out[((b * 64 + c) * 256 + h) * 256 + w] = sm[oOut + idx];
    }
}

extern "C" void kernel_launch(void* const* d_in, const int* in_sizes, int n_in,
                              void* d_out, int out_size) {
    const float* x1 = (const float*)d_in[0];
    const float* x2 = (const float*)d_in[1];
    const float* Wk = (const float*)d_in[2];
    const float* bk = (const float*)d_in[3];
    const float* Wv = (const float*)d_in[4];
    const float* bv = (const float*)d_in[5];
    const float* Wp = (const float*)d_in[6];
    const float* bp = (const float*)d_in[7];
    float* out = (float*)d_out;

    repack_kernel<<<32, 256>>>(Wk, Wv, Wp);

    cudaFuncSetAttribute(fused_kernel,
                         cudaFuncAttributeMaxDynamicSharedMemorySize, SMEM_BYTES);
    fused_kernel<<<N_ATTN + N_FILL, BDIM, SMEM_BYTES>>>(x1, x2, Wk, bk, Wv, bv, Wp, bp, out);
}